// round 13
// baseline (speedup 1.0000x reference)
#include <cuda_runtime.h>
#include <cuda_bf16.h>
#include <cuda_fp8.h>
#include <math.h>
#include <stdint.h>

#define NN 8192
#define DD 1024

// ---------------- scratch (allocation-free rule) ----------------
__device__ uint8_t g_emb8[(size_t)NN * DD];   // normalized emb * 32, e4m3, 8MB
__device__ float g_sum[NN];
__device__ float g_pos[NN];

// ---------------- geometry ----------------
#define BM 128
#define BN 128
#define STAGES 4
#define NSM 152
#define NJOBS 4096                // 64x64 tiles
#define KCHUNK 128                // fp8 elems per chunk = 128 B row
#define KSTEPS 8                  // 1024 / 128
#define ROWBYTES 144              // 128B data + 16B pad (conflict-free LDSM)
#define TILE_BYTES (128 * ROWBYTES)       // 18432
#define STAGE_BYTES (2 * TILE_BYTES)      // A + B

#define QSCALE 32.0f
#define INVT_ACC ((1.0f / 0.07f) / (QSCALE * QSCALE))

// dynamic smem layout (bytes)
#define SM_COLLAB   0                         // int[2][128]
#define SM_A(s)     (2048 + (s) * STAGE_BYTES)
#define SM_B(s)     (SM_A(s) + TILE_BYTES)
#define SMEM_TOTAL  (2048 + STAGES * STAGE_BYTES)   // 149504

// ---------------- PTX helpers ----------------
#define CP_ASYNC16(dst_u32, src_ptr) \
    asm volatile("cp.async.cg.shared.global [%0], [%1], 16;" \
                 :: "r"(dst_u32), "l"(src_ptr) : "memory")
#define CP_COMMIT() asm volatile("cp.async.commit_group;" ::: "memory")

#define LDSM_X4(r0, r1, r2, r3, addr) \
    asm volatile("ldmatrix.sync.aligned.m8n8.x4.shared.b16 {%0,%1,%2,%3}, [%4];" \
                 : "=r"(r0), "=r"(r1), "=r"(r2), "=r"(r3) : "r"(addr))

#define MMA16832F8(d, a, b) \
    asm volatile("mma.sync.aligned.m16n8k32.row.col.f32.e4m3.e4m3.f32 " \
                 "{%0,%1,%2,%3}, {%4,%5,%6,%7}, {%8,%9}, {%0,%1,%2,%3};" \
                 : "+f"((d)[0]), "+f"((d)[1]), "+f"((d)[2]), "+f"((d)[3]) \
                 : "r"((a)[0]), "r"((a)[1]), "r"((a)[2]), "r"((a)[3]), \
                   "r"((b)[0]), "r"((b)[1]))

// ---------------------------------------------------------------------------
// Kernel 1: L2-normalize rows -> e4m3 * QSCALE (+ zero accumulators)
// ---------------------------------------------------------------------------
__global__ void __launch_bounds__(256) norm_kernel(const float* __restrict__ in) {
    int row = blockIdx.x;
    if (threadIdx.x == 0) { g_sum[row] = 0.f; g_pos[row] = 0.f; }
    float4 v = ((const float4*)(in + (size_t)row * DD))[threadIdx.x];
    float s = v.x * v.x + v.y * v.y + v.z * v.z + v.w * v.w;
    #pragma unroll
    for (int o = 16; o > 0; o >>= 1) s += __shfl_xor_sync(0xffffffffu, s, o);
    __shared__ float ws[8];
    int lane = threadIdx.x & 31, w = threadIdx.x >> 5;
    if (lane == 0) ws[w] = s;
    __syncthreads();
    if (threadIdx.x == 0) {
        float t = 0.f;
        #pragma unroll
        for (int i = 0; i < 8; i++) t += ws[i];
        ws[0] = QSCALE / fmaxf(sqrtf(t), 1e-12f);
    }
    __syncthreads();
    float inv = ws[0];
    uint32_t packed =
        (uint32_t)__nv_cvt_float_to_fp8(v.x * inv, __NV_SATFINITE, __NV_E4M3)
        | ((uint32_t)__nv_cvt_float_to_fp8(v.y * inv, __NV_SATFINITE, __NV_E4M3) << 8)
        | ((uint32_t)__nv_cvt_float_to_fp8(v.z * inv, __NV_SATFINITE, __NV_E4M3) << 16)
        | ((uint32_t)__nv_cvt_float_to_fp8(v.w * inv, __NV_SATFINITE, __NV_E4M3) << 24);
    *(uint32_t*)(g_emb8 + (size_t)row * DD + threadIdx.x * 4) = packed;
}

// ---------------------------------------------------------------------------
// Kernel 2: persistent CTAs, 512 threads = 16 warps (4x4), warp tile 32x32,
// fp8 m16n8k32 -> fp32, 4-stage cp.async pipeline warm across tiles.
// ---------------------------------------------------------------------------
__global__ void __launch_bounds__(512, 1) sim_kernel(const int* __restrict__ labels) {
    extern __shared__ char smem[];
    const uint32_t sb = (uint32_t)__cvta_generic_to_shared(smem);
    int* colLab = (int*)(smem + SM_COLLAB);    // [2][128] by job parity

    const int tid = threadIdx.x;
    const int lane = tid & 31;
    const int wid = tid >> 5;
    const int wr = wid >> 2;          // 0..3 (row group of 32)
    const int wc = wid & 3;           // 0..3 (col group of 32)
    const int bid = blockIdx.x;

    const int myJobs = 26 + (bid < (NJOBS - NSM * 26) ? 1 : 0);  // 27 or 26
    const int total = myJobs * KSTEPS;

    int rlRows[4];
    #pragma unroll
    for (int mf = 0; mf < 2; mf++)
        #pragma unroll
        for (int h = 0; h < 2; h++)
            rlRows[mf * 2 + h] = wr * 32 + mf * 16 + (lane >> 2) + h * 8;

    // cp.async mapping: 512 threads, per chunk each thread moves 2 A + 2 B words
    const int ldRow = tid >> 3;         // 0..63 (+i*64)
    const int ldChunk = tid & 7;        // 16B word within the 128B row

    // ---- preload chunks 0..2 of job 0 ----
    {
        const int rB = (bid >> 6) * BM;
        const int cB = (bid & 63) * BN;
        #pragma unroll
        for (int ps = 0; ps < STAGES - 1; ps++) {
            const int kOff = ps * KCHUNK;
            #pragma unroll
            for (int i = 0; i < 2; i++) {
                const int row = ldRow + i * 64;
                CP_ASYNC16(sb + SM_A(ps) + row * ROWBYTES + ldChunk * 16,
                           g_emb8 + (size_t)(rB + row) * DD + kOff + ldChunk * 16);
            }
            #pragma unroll
            for (int i = 0; i < 2; i++) {
                const int row = ldRow + i * 64;
                CP_ASYNC16(sb + SM_B(ps) + row * ROWBYTES + ldChunk * 16,
                           g_emb8 + (size_t)(cB + row) * DD + kOff + ldChunk * 16);
            }
            CP_COMMIT();
        }
    }

    const float diagE = expf(1.0f / 0.07f);

    float acc[2][4][4];
    int rlab[4];

    #pragma unroll 1
    for (int c = 0; c < total; c++) {
        const int jl = c >> 3;
        const int ks = c & 7;
        const int jid = bid + NSM * jl;
        const int rowBase = (jid >> 6) * BM;
        const int colBase = (jid & 63) * BN;

        if (c < total - 2)       asm volatile("cp.async.wait_group 2;" ::: "memory");
        else if (c == total - 2) asm volatile("cp.async.wait_group 1;" ::: "memory");
        else                     asm volatile("cp.async.wait_group 0;" ::: "memory");
        __syncthreads();   // publishes stage c; retires reads of stage (c+3)&3

        if (ks == 0) {
            if (tid < BN) colLab[(jl & 1) * 128 + tid] = labels[colBase + tid];
            #pragma unroll
            for (int li = 0; li < 4; li++) rlab[li] = labels[rowBase + rlRows[li]];
            #pragma unroll
            for (int mf = 0; mf < 2; mf++)
                #pragma unroll
                for (int nf = 0; nf < 4; nf++)
                    #pragma unroll
                    for (int e = 0; e < 4; e++) acc[mf][nf][e] = 0.f;
        }

        // prefetch chunk c+3 (crosses job boundaries — pipeline never drains)
        {
            const int n = c + 3;
            if (n < total) {
                const int jid2 = bid + NSM * (n >> 3);
                const int rB2 = (jid2 >> 6) * BM;
                const int cB2 = (jid2 & 63) * BN;
                const int s2 = n & 3;
                const int kOff = (n & 7) * KCHUNK;
                #pragma unroll
                for (int i = 0; i < 2; i++) {
                    const int row = ldRow + i * 64;
                    CP_ASYNC16(sb + SM_A(s2) + row * ROWBYTES + ldChunk * 16,
                               g_emb8 + (size_t)(rB2 + row) * DD + kOff + ldChunk * 16);
                }
                #pragma unroll
                for (int i = 0; i < 2; i++) {
                    const int row = ldRow + i * 64;
                    CP_ASYNC16(sb + SM_B(s2) + row * ROWBYTES + ldChunk * 16,
                               g_emb8 + (size_t)(cB2 + row) * DD + kOff + ldChunk * 16);
                }
                CP_COMMIT();
            }
        }

        // ---- compute chunk c: 4 x k32 fp8 MMA groups ----
        const int buf = c & 3;
        const uint32_t aBase = sb + SM_A(buf);
        const uint32_t bBase = sb + SM_B(buf);
        #pragma unroll
        for (int kg = 0; kg < 4; kg++) {
            const uint32_t colByte = kg * 32 + (lane >> 4) * 16;
            uint32_t a[2][4], b[4][2];
            #pragma unroll
            for (int mf = 0; mf < 2; mf++) {
                const uint32_t addr =
                    aBase + (wr * 32 + mf * 16 + (lane & 15)) * ROWBYTES + colByte;
                LDSM_X4(a[mf][0], a[mf][1], a[mf][2], a[mf][3], addr);
            }
            #pragma unroll
            for (int nb = 0; nb < 2; nb++) {
                uint32_t r0, r1, r2, r3;
                const uint32_t addr =
                    bBase + (wc * 32 + nb * 16 + (lane & 15)) * ROWBYTES + colByte;
                LDSM_X4(r0, r1, r2, r3, addr);
                b[nb * 2][0] = r0;     b[nb * 2][1] = r2;
                b[nb * 2 + 1][0] = r1; b[nb * 2 + 1][1] = r3;
            }
            #pragma unroll
            for (int mf = 0; mf < 2; mf++)
                #pragma unroll
                for (int nf = 0; nf < 4; nf++)
                    MMA16832F8(acc[mf][nf], a[mf], b[nf]);
        }

        // ---- epilogue at end of job (overlaps with next job's prefetch) ----
        if (ks == KSTEPS - 1) {
            const int* cl2 = colLab + (jl & 1) * 128;
            float sumL[4] = {0.f, 0.f, 0.f, 0.f};
            float posL[4] = {0.f, 0.f, 0.f, 0.f};
            #pragma unroll
            for (int mf = 0; mf < 2; mf++) {
                #pragma unroll
                for (int nf = 0; nf < 4; nf++) {
                    #pragma unroll
                    for (int e = 0; e < 4; e++) {
                        const int h = e >> 1;
                        const int li = mf * 2 + h;
                        const int cl = wc * 32 + nf * 8 + (lane & 3) * 2 + (e & 1);
                        const int cg = colBase + cl;
                        const int rg = rowBase + rlRows[li];
                        const float ev = __expf(acc[mf][nf][e] * INVT_ACC);
                        const bool diag = (cg == rg);
                        sumL[li] += diag ? diagE : ev;
                        if (!diag && cl2[cl] == rlab[li]) posL[li] += ev;
                    }
                }
            }
            #pragma unroll
            for (int li = 0; li < 4; li++) {
                float s = sumL[li], p = posL[li];
                s += __shfl_xor_sync(0xffffffffu, s, 1);
                s += __shfl_xor_sync(0xffffffffu, s, 2);
                p += __shfl_xor_sync(0xffffffffu, p, 1);
                p += __shfl_xor_sync(0xffffffffu, p, 2);
                if ((lane & 3) == 0) {
                    atomicAdd(&g_sum[rowBase + rlRows[li]], s);
                    atomicAdd(&g_pos[rowBase + rlRows[li]], p);
                }
            }
        }
    }
}

// ---------------------------------------------------------------------------
// Kernel 3: per-row loss + mean
// ---------------------------------------------------------------------------
__global__ void __launch_bounds__(1024) reduce_kernel(float* __restrict__ out) {
    float acc = 0.f;
    for (int i = threadIdx.x; i < NN; i += 1024)
        acc += logf(g_sum[i]) - logf(g_pos[i]);
    #pragma unroll
    for (int o = 16; o > 0; o >>= 1) acc += __shfl_xor_sync(0xffffffffu, acc, o);
    __shared__ float ws[32];
    int lane = threadIdx.x & 31, w = threadIdx.x >> 5;
    if (lane == 0) ws[w] = acc;
    __syncthreads();
    if (threadIdx.x == 0) {
        float t = 0.f;
        #pragma unroll
        for (int i = 0; i < 32; i++) t += ws[i];
        out[0] = t / (float)NN;
    }
}

extern "C" void kernel_launch(void* const* d_in, const int* in_sizes, int n_in,
                              void* d_out, int out_size) {
    const float* emb = (const float*)d_in[0];
    const int* labels = (const int*)d_in[1];
    cudaFuncSetAttribute(sim_kernel, cudaFuncAttributeMaxDynamicSharedMemorySize, SMEM_TOTAL);
    norm_kernel<<<NN, 256>>>(emb);
    sim_kernel<<<NSM, 512, SMEM_TOTAL>>>(labels);
    reduce_kernel<<<1, 1024>>>((float*)d_out);
}

// round 17
// speedup vs baseline: 1.6913x; 1.6913x over previous
#include <cuda_runtime.h>
#include <cuda_bf16.h>
#include <cuda_fp8.h>
#include <math.h>
#include <stdint.h>

#define NN 8192
#define DD 1024

// ---------------- scratch (allocation-free rule) ----------------
__device__ uint8_t g_emb8[(size_t)NN * DD];   // normalized emb * 32, e4m3, 8MB
__device__ float g_sum[NN];
__device__ float g_pos[NN];

// ---------------- geometry ----------------
#define BM 128
#define BN 128
#define STAGES 3
#define NCTA 304                  // 2 CTAs per SM x 152 SMs
#define NJOBS 4096                // 64x64 tiles
#define KCHUNK 128                // fp8 elems per chunk = 128 B row
#define KSTEPS 8                  // 1024 / 128
#define ROWBYTES 144              // 128B data + 16B pad (conflict-free LDSM)
#define TILE_BYTES (128 * ROWBYTES)       // 18432
#define STAGE_BYTES (2 * TILE_BYTES)      // A + B

#define QSCALE 32.0f
#define INVT_ACC ((1.0f / 0.07f) / (QSCALE * QSCALE))

// dynamic smem layout (bytes): 2048 + 3*36864 = 112640 (fits 2 CTAs in 228KB/SM)
#define SM_COLLAB   0                         // int[2][128]
#define SM_A(s)     (2048 + (s) * STAGE_BYTES)
#define SM_B(s)     (SM_A(s) + TILE_BYTES)
#define SMEM_TOTAL  (2048 + STAGES * STAGE_BYTES)

// ---------------- PTX helpers ----------------
#define CP_ASYNC16(dst_u32, src_ptr) \
    asm volatile("cp.async.cg.shared.global [%0], [%1], 16;" \
                 :: "r"(dst_u32), "l"(src_ptr) : "memory")
#define CP_COMMIT() asm volatile("cp.async.commit_group;" ::: "memory")

#define LDSM_X4(r0, r1, r2, r3, addr) \
    asm volatile("ldmatrix.sync.aligned.m8n8.x4.shared.b16 {%0,%1,%2,%3}, [%4];" \
                 : "=r"(r0), "=r"(r1), "=r"(r2), "=r"(r3) : "r"(addr))

#define MMA16832F8(d, a, b) \
    asm volatile("mma.sync.aligned.m16n8k32.row.col.f32.e4m3.e4m3.f32 " \
                 "{%0,%1,%2,%3}, {%4,%5,%6,%7}, {%8,%9}, {%0,%1,%2,%3};" \
                 : "+f"((d)[0]), "+f"((d)[1]), "+f"((d)[2]), "+f"((d)[3]) \
                 : "r"((a)[0]), "r"((a)[1]), "r"((a)[2]), "r"((a)[3]), \
                   "r"((b)[0]), "r"((b)[1]))

// ---------------------------------------------------------------------------
// Kernel 1: L2-normalize rows -> e4m3 * QSCALE (+ zero accumulators)
// ---------------------------------------------------------------------------
__global__ void __launch_bounds__(256) norm_kernel(const float* __restrict__ in) {
    int row = blockIdx.x;
    if (threadIdx.x == 0) { g_sum[row] = 0.f; g_pos[row] = 0.f; }
    float4 v = ((const float4*)(in + (size_t)row * DD))[threadIdx.x];
    float s = v.x * v.x + v.y * v.y + v.z * v.z + v.w * v.w;
    #pragma unroll
    for (int o = 16; o > 0; o >>= 1) s += __shfl_xor_sync(0xffffffffu, s, o);
    __shared__ float ws[8];
    int lane = threadIdx.x & 31, w = threadIdx.x >> 5;
    if (lane == 0) ws[w] = s;
    __syncthreads();
    if (threadIdx.x == 0) {
        float t = 0.f;
        #pragma unroll
        for (int i = 0; i < 8; i++) t += ws[i];
        ws[0] = QSCALE / fmaxf(sqrtf(t), 1e-12f);
    }
    __syncthreads();
    float inv = ws[0];
    uint32_t packed =
        (uint32_t)__nv_cvt_float_to_fp8(v.x * inv, __NV_SATFINITE, __NV_E4M3)
        | ((uint32_t)__nv_cvt_float_to_fp8(v.y * inv, __NV_SATFINITE, __NV_E4M3) << 8)
        | ((uint32_t)__nv_cvt_float_to_fp8(v.z * inv, __NV_SATFINITE, __NV_E4M3) << 16)
        | ((uint32_t)__nv_cvt_float_to_fp8(v.w * inv, __NV_SATFINITE, __NV_E4M3) << 24);
    *(uint32_t*)(g_emb8 + (size_t)row * DD + threadIdx.x * 4) = packed;
}

// ---------------------------------------------------------------------------
// Kernel 2: persistent CTAs, 2 per SM. 256 threads = 8 warps (4x2), warp tile
// 32x64, fp8 m16n8k32 -> fp32, 3-stage cp.async pipeline warm across tiles.
// ---------------------------------------------------------------------------
__global__ void __launch_bounds__(256, 2) sim_kernel(const int* __restrict__ labels) {
    extern __shared__ char smem[];
    const uint32_t sb = (uint32_t)__cvta_generic_to_shared(smem);
    int* colLab = (int*)(smem + SM_COLLAB);    // [2][128] by job parity

    const int tid = threadIdx.x;
    const int lane = tid & 31;
    const int wid = tid >> 5;
    const int wr = wid >> 1;          // 0..3
    const int wc = wid & 1;           // 0..1
    const int bid = blockIdx.x;

    // 4096 = 304*13 + 144 -> first 144 CTAs take 14 jobs, rest 13
    const int myJobs = 13 + (bid < (NJOBS - NCTA * 13) ? 1 : 0);
    const int total = myJobs * KSTEPS;

    int rlRows[4];
    #pragma unroll
    for (int mf = 0; mf < 2; mf++)
        #pragma unroll
        for (int h = 0; h < 2; h++)
            rlRows[mf * 2 + h] = wr * 32 + mf * 16 + (lane >> 2) + h * 8;

    // cp.async mapping: per chunk each thread moves 4 A + 4 B 16B words
    const int ldRow = tid >> 3;         // 0..31 (+i*32)
    const int ldChunk = tid & 7;        // 16B word within the 128B row

    // ---- preload chunks 0..1 of job 0 ----
    {
        const int rB = (bid >> 6) * BM;
        const int cB = (bid & 63) * BN;
        #pragma unroll
        for (int ps = 0; ps < STAGES - 1; ps++) {
            const int kOff = ps * KCHUNK;
            #pragma unroll
            for (int i = 0; i < 4; i++) {
                const int row = ldRow + i * 32;
                CP_ASYNC16(sb + SM_A(ps) + row * ROWBYTES + ldChunk * 16,
                           g_emb8 + (size_t)(rB + row) * DD + kOff + ldChunk * 16);
            }
            #pragma unroll
            for (int i = 0; i < 4; i++) {
                const int row = ldRow + i * 32;
                CP_ASYNC16(sb + SM_B(ps) + row * ROWBYTES + ldChunk * 16,
                           g_emb8 + (size_t)(cB + row) * DD + kOff + ldChunk * 16);
            }
            CP_COMMIT();
        }
    }

    const float diagE = expf(1.0f / 0.07f);

    float acc[2][8][4];
    int rlab[4];

    #pragma unroll 1
    for (int c = 0; c < total; c++) {
        const int jl = c >> 3;
        const int ks = c & 7;
        const int jid = bid + NCTA * jl;
        const int rowBase = (jid >> 6) * BM;
        const int colBase = (jid & 63) * BN;

        // chunk c resident when pending <= (groups issued after c)
        if (c < total - 1) asm volatile("cp.async.wait_group 1;" ::: "memory");
        else               asm volatile("cp.async.wait_group 0;" ::: "memory");
        __syncthreads();   // publishes stage c; retires reads of stage (c+2)%3

        if (ks == 0) {
            if (tid < BN) colLab[(jl & 1) * 128 + tid] = labels[colBase + tid];
            #pragma unroll
            for (int li = 0; li < 4; li++) rlab[li] = labels[rowBase + rlRows[li]];
            #pragma unroll
            for (int mf = 0; mf < 2; mf++)
                #pragma unroll
                for (int nf = 0; nf < 8; nf++)
                    #pragma unroll
                    for (int e = 0; e < 4; e++) acc[mf][nf][e] = 0.f;
        }

        // prefetch chunk c+2 (crosses job boundaries — pipeline never drains)
        {
            const int n = c + 2;
            if (n < total) {
                const int jid2 = bid + NCTA * (n >> 3);
                const int rB2 = (jid2 >> 6) * BM;
                const int cB2 = (jid2 & 63) * BN;
                const int s2 = n % STAGES;
                const int kOff = (n & 7) * KCHUNK;
                #pragma unroll
                for (int i = 0; i < 4; i++) {
                    const int row = ldRow + i * 32;
                    CP_ASYNC16(sb + SM_A(s2) + row * ROWBYTES + ldChunk * 16,
                               g_emb8 + (size_t)(rB2 + row) * DD + kOff + ldChunk * 16);
                }
                #pragma unroll
                for (int i = 0; i < 4; i++) {
                    const int row = ldRow + i * 32;
                    CP_ASYNC16(sb + SM_B(s2) + row * ROWBYTES + ldChunk * 16,
                               g_emb8 + (size_t)(cB2 + row) * DD + kOff + ldChunk * 16);
                }
                CP_COMMIT();
            }
        }

        // ---- compute chunk c: 4 x k32 fp8 MMA groups over the 128B rows ----
        const int buf = c % STAGES;
        const uint32_t aBase = sb + SM_A(buf);
        const uint32_t bBase = sb + SM_B(buf);
        #pragma unroll
        for (int kg = 0; kg < 4; kg++) {
            const uint32_t colByte = kg * 32 + (lane >> 4) * 16;
            uint32_t a[2][4], b[8][2];
            #pragma unroll
            for (int mf = 0; mf < 2; mf++) {
                const uint32_t addr =
                    aBase + (wr * 32 + mf * 16 + (lane & 15)) * ROWBYTES + colByte;
                LDSM_X4(a[mf][0], a[mf][1], a[mf][2], a[mf][3], addr);
            }
            #pragma unroll
            for (int nb = 0; nb < 4; nb++) {
                uint32_t r0, r1, r2, r3;
                const uint32_t addr =
                    bBase + (wc * 64 + nb * 16 + (lane & 15)) * ROWBYTES + colByte;
                LDSM_X4(r0, r1, r2, r3, addr);
                b[nb * 2][0] = r0;     b[nb * 2][1] = r2;
                b[nb * 2 + 1][0] = r1; b[nb * 2 + 1][1] = r3;
            }
            #pragma unroll
            for (int mf = 0; mf < 2; mf++)
                #pragma unroll
                for (int nf = 0; nf < 8; nf++)
                    MMA16832F8(acc[mf][nf], a[mf], b[nf]);
        }

        // ---- epilogue at end of job (overlaps with next job's prefetch) ----
        if (ks == KSTEPS - 1) {
            const int* cl2 = colLab + (jl & 1) * 128;
            float sumL[4] = {0.f, 0.f, 0.f, 0.f};
            float posL[4] = {0.f, 0.f, 0.f, 0.f};
            #pragma unroll
            for (int mf = 0; mf < 2; mf++) {
                #pragma unroll
                for (int nf = 0; nf < 8; nf++) {
                    #pragma unroll
                    for (int e = 0; e < 4; e++) {
                        const int h = e >> 1;
                        const int li = mf * 2 + h;
                        const int cl = wc * 64 + nf * 8 + (lane & 3) * 2 + (e & 1);
                        const int cg = colBase + cl;
                        const int rg = rowBase + rlRows[li];
                        const float ev = __expf(acc[mf][nf][e] * INVT_ACC);
                        const bool diag = (cg == rg);
                        sumL[li] += diag ? diagE : ev;
                        if (!diag && cl2[cl] == rlab[li]) posL[li] += ev;
                    }
                }
            }
            #pragma unroll
            for (int li = 0; li < 4; li++) {
                float s = sumL[li], p = posL[li];
                s += __shfl_xor_sync(0xffffffffu, s, 1);
                s += __shfl_xor_sync(0xffffffffu, s, 2);
                p += __shfl_xor_sync(0xffffffffu, p, 1);
                p += __shfl_xor_sync(0xffffffffu, p, 2);
                if ((lane & 3) == 0) {
                    atomicAdd(&g_sum[rowBase + rlRows[li]], s);
                    atomicAdd(&g_pos[rowBase + rlRows[li]], p);
                }
            }
        }
    }
}

// ---------------------------------------------------------------------------
// Kernel 3: per-row loss + mean
// ---------------------------------------------------------------------------
__global__ void __launch_bounds__(1024) reduce_kernel(float* __restrict__ out) {
    float acc = 0.f;
    for (int i = threadIdx.x; i < NN; i += 1024)
        acc += logf(g_sum[i]) - logf(g_pos[i]);
    #pragma unroll
    for (int o = 16; o > 0; o >>= 1) acc += __shfl_xor_sync(0xffffffffu, acc, o);
    __shared__ float ws[32];
    int lane = threadIdx.x & 31, w = threadIdx.x >> 5;
    if (lane == 0) ws[w] = acc;
    __syncthreads();
    if (threadIdx.x == 0) {
        float t = 0.f;
        #pragma unroll
        for (int i = 0; i < 32; i++) t += ws[i];
        out[0] = t / (float)NN;
    }
}

extern "C" void kernel_launch(void* const* d_in, const int* in_sizes, int n_in,
                              void* d_out, int out_size) {
    const float* emb = (const float*)d_in[0];
    const int* labels = (const int*)d_in[1];
    cudaFuncSetAttribute(sim_kernel, cudaFuncAttributeMaxDynamicSharedMemorySize, SMEM_TOTAL);
    norm_kernel<<<NN, 256>>>(emb);
    sim_kernel<<<NCTA, 256, SMEM_TOTAL>>>(labels);
    reduce_kernel<<<1, 1024>>>((float*)d_out);
}